// round 5
// baseline (speedup 1.0000x reference)
#include <cuda_runtime.h>
#include <math.h>

#define B_  16
#define S_  4096
#define E_  2048
#define H_  16
#define D_  128
#define SPLITS 8
#define NPART (SPLITS * 4)        // 4 warps per block each emit a partial
#define SCALE 0.08838834764831845f // 1/sqrt(128)

// ---- scratch (no allocation allowed) ----
__device__ float g_q[B_ * E_];
__device__ float g_ctx[B_ * E_];
__device__ float g_pm[B_ * H_ * NPART];
__device__ float g_pl[B_ * H_ * NPART];
__device__ float g_pctx[B_ * H_ * NPART * D_];

// ---------------------------------------------------------------------------
// Projection: out[b,e] = sum_i x[b,i] * W[e,i] + bias[e]
// One warp per output column e, all 16 batches accumulated together so W is
// read exactly once from DRAM (16 MB).
// ---------------------------------------------------------------------------
__global__ void proj_kernel(const float* __restrict__ x,
                            const float* __restrict__ W,
                            const float* __restrict__ bias,
                            float* __restrict__ out) {
    int e    = blockIdx.x * 8 + (threadIdx.x >> 5);
    int lane = threadIdx.x & 31;
    const float* wrow = W + (size_t)e * E_;

    float acc[B_];
#pragma unroll
    for (int b = 0; b < B_; b++) acc[b] = 0.f;

    for (int i = lane; i < E_; i += 32) {
        float w = wrow[i];
#pragma unroll
        for (int b = 0; b < B_; b++) acc[b] += w * x[b * E_ + i];
    }
    float bv = bias[e];
#pragma unroll
    for (int b = 0; b < B_; b++) {
        float v = acc[b];
#pragma unroll
        for (int off = 16; off > 0; off >>= 1) v += __shfl_xor_sync(0xffffffffu, v, off);
        if (lane == 0) out[b * E_ + e] = v + bv;
    }
}

// ---------------------------------------------------------------------------
// Fused flash-decode split-S attention. Each warp handles 128 rows of its
// (b,h,split) chunk with an online softmax; k/v float4s are simultaneously
// streamed to the d_out cache regions (each element touched exactly once).
// ---------------------------------------------------------------------------
__global__ void attn_kernel(const float* __restrict__ q,
                            const float* __restrict__ kc,
                            const float* __restrict__ vc,
                            float* __restrict__ outk,
                            float* __restrict__ outv) {
    const int split = blockIdx.x;
    const int h     = blockIdx.y;
    const int b     = blockIdx.z;
    const int warp  = threadIdx.x >> 5;
    const int lane  = threadIdx.x & 31;

    const size_t base = (size_t)b * S_ * H_ * D_ + (size_t)h * D_ + (size_t)lane * 4;

    float4 q4 = *(const float4*)(q + (size_t)b * E_ + h * D_ + lane * 4);

    float  m = -INFINITY, l = 0.f;
    float4 acc = make_float4(0.f, 0.f, 0.f, 0.f);

    const int s0 = split * (S_ / SPLITS) + warp;
    const bool wr = (outk != nullptr);

#pragma unroll 4
    for (int i = 0; i < (S_ / SPLITS) / 4; i++) {
        const int s = s0 + 4 * i;
        const size_t off = base + (size_t)s * (H_ * D_);
        float4 k4 = *(const float4*)(kc + off);
        float4 v4 = *(const float4*)(vc + off);
        if (wr) {
            *(float4*)(outk + off) = k4;
            *(float4*)(outv + off) = v4;
        }
        float sc = q4.x * k4.x + q4.y * k4.y + q4.z * k4.z + q4.w * k4.w;
#pragma unroll
        for (int o = 16; o > 0; o >>= 1) sc += __shfl_xor_sync(0xffffffffu, sc, o);
        sc *= SCALE;

        float mn   = fmaxf(m, sc);
        float corr = __expf(m - mn);
        float p    = __expf(sc - mn);
        l = l * corr + p;
        acc.x = acc.x * corr + p * v4.x;
        acc.y = acc.y * corr + p * v4.y;
        acc.z = acc.z * corr + p * v4.z;
        acc.w = acc.w * corr + p * v4.w;
        m = mn;
    }

    const int pidx = ((b * H_ + h) * SPLITS + split) * 4 + warp;
    if (lane == 0) { g_pm[pidx] = m; g_pl[pidx] = l; }
    *(float4*)(g_pctx + (size_t)pidx * D_ + lane * 4) = acc;
}

// ---------------------------------------------------------------------------
// Combine NPART partials per (b,h) into normalized context.
// ---------------------------------------------------------------------------
__global__ void combine_kernel(float* __restrict__ ctx) {
    const int bh = blockIdx.x;   // b*H + h
    const int d  = threadIdx.x;  // 0..127

    float M = -INFINITY;
#pragma unroll
    for (int p = 0; p < NPART; p++) M = fmaxf(M, g_pm[bh * NPART + p]);

    float L = 0.f, c = 0.f;
#pragma unroll
    for (int p = 0; p < NPART; p++) {
        float w = __expf(g_pm[bh * NPART + p] - M);
        L += w * g_pl[bh * NPART + p];
        c += w * g_pctx[(size_t)(bh * NPART + p) * D_ + d];
    }
    ctx[(size_t)bh * D_ + d] = c / L;   // ctx[b*E + h*128 + d] since E = H*D
}

// ---------------------------------------------------------------------------
extern "C" void kernel_launch(void* const* d_in, const int* in_sizes, int n_in,
                              void* d_out, int out_size) {
    const float* x  = (const float*)d_in[0];
    const float* kc = (const float*)d_in[1];
    const float* vc = (const float*)d_in[2];
    const float* Wq = (const float*)d_in[3];
    const float* bq = (const float*)d_in[4];
    // Wk/bk/Wv/bv (d_in[5..8]) are dead in the reference — never used.
    const float* Wo = (const float*)d_in[9];
    const float* bo = (const float*)d_in[10];

    float* out = (float*)d_out;
    const size_t cache_elems = (size_t)B_ * S_ * H_ * D_;

    float* outk = nullptr;
    float* outv = nullptr;
    if ((size_t)out_size >= (size_t)B_ * E_ + 2 * cache_elems) {
        outk = out + B_ * E_;
        outv = outk + cache_elems;
    }

    // 1) Q projection
    proj_kernel<<<E_ / 8, 256>>>(x, Wq, bq, g_q);

    // 2) Fused attention + cache copy-out
    dim3 ag(SPLITS, H_, B_);
    attn_kernel<<<ag, 128>>>(g_q, kc, vc, outk, outv);

    // 3) Combine split partials
    combine_kernel<<<B_ * H_, D_>>>(g_ctx);

    // 4) Output projection
    proj_kernel<<<E_ / 8, 256>>>(g_ctx, Wo, bo, out);
}

// round 9
// speedup vs baseline: 1.1210x; 1.1210x over previous
#include <cuda_runtime.h>
#include <math.h>

#define B_  16
#define S_  4096
#define E_  2048
#define H_  16
#define D_  128
#define SPLITS 8
#define NPART (SPLITS * 4)        // 4 warps per block each emit a partial
#define SCALE 0.08838834764831845f // 1/sqrt(128)

// ---- scratch (no allocation allowed) ----
__device__ float g_q[B_ * E_];
__device__ float g_ctx[B_ * E_];
__device__ float g_pm[B_ * H_ * NPART];
__device__ float g_pl[B_ * H_ * NPART];
__device__ float g_pctx[B_ * H_ * NPART * D_];

// ---------------------------------------------------------------------------
// Projection: out[b,e] = sum_i x[b,i] * W[e,i] + bias[e]
// One warp per output column e. float4 loads + full unroll of the 16 chunks
// so ptxas front-batches the W loads (high MLP -> cover DRAM latency).
// x is 128 KB and L1-resident after the first pass.
// ---------------------------------------------------------------------------
__global__ void __launch_bounds__(256) proj_kernel(
        const float* __restrict__ x,
        const float* __restrict__ W,
        const float* __restrict__ bias,
        float* __restrict__ out) {
    const int e    = blockIdx.x * 8 + (threadIdx.x >> 5);
    const int lane = threadIdx.x & 31;

    const float4* __restrict__ w4 = (const float4*)(W + (size_t)e * E_);
    const float4* __restrict__ x4 = (const float4*)x;

    float acc[B_];
#pragma unroll
    for (int b = 0; b < B_; b++) acc[b] = 0.f;

#pragma unroll
    for (int c = 0; c < E_ / 128; c++) {           // 16 chunks, fully unrolled
        const int idx = c * 32 + lane;
        float4 w = w4[idx];
#pragma unroll
        for (int b = 0; b < B_; b++) {
            float4 xv = x4[b * (E_ / 4) + idx];
            acc[b] += w.x * xv.x + w.y * xv.y + w.z * xv.z + w.w * xv.w;
        }
    }

    const float bv = bias[e];
#pragma unroll
    for (int b = 0; b < B_; b++) {
        float v = acc[b];
#pragma unroll
        for (int off = 16; off > 0; off >>= 1) v += __shfl_xor_sync(0xffffffffu, v, off);
        if (lane == 0) out[b * E_ + e] = v + bv;
    }
}

// ---------------------------------------------------------------------------
// Fused flash-decode split-S attention. Each warp handles 128 rows of its
// (b,h,split) chunk with an online softmax; k/v float4s are simultaneously
// streamed to the d_out cache regions (each element touched exactly once).
// Already at the HBM roofline (~8 TB/s effective).
// ---------------------------------------------------------------------------
__global__ void attn_kernel(const float* __restrict__ q,
                            const float* __restrict__ kc,
                            const float* __restrict__ vc,
                            float* __restrict__ outk,
                            float* __restrict__ outv) {
    const int split = blockIdx.x;
    const int h     = blockIdx.y;
    const int b     = blockIdx.z;
    const int warp  = threadIdx.x >> 5;
    const int lane  = threadIdx.x & 31;

    const size_t base = (size_t)b * S_ * H_ * D_ + (size_t)h * D_ + (size_t)lane * 4;

    float4 q4 = *(const float4*)(q + (size_t)b * E_ + h * D_ + lane * 4);

    float  m = -INFINITY, l = 0.f;
    float4 acc = make_float4(0.f, 0.f, 0.f, 0.f);

    const int s0 = split * (S_ / SPLITS) + warp;
    const bool wr = (outk != nullptr);

#pragma unroll 4
    for (int i = 0; i < (S_ / SPLITS) / 4; i++) {
        const int s = s0 + 4 * i;
        const size_t off = base + (size_t)s * (H_ * D_);
        float4 k4 = *(const float4*)(kc + off);
        float4 v4 = *(const float4*)(vc + off);
        if (wr) {
            *(float4*)(outk + off) = k4;
            *(float4*)(outv + off) = v4;
        }
        float sc = q4.x * k4.x + q4.y * k4.y + q4.z * k4.z + q4.w * k4.w;
#pragma unroll
        for (int o = 16; o > 0; o >>= 1) sc += __shfl_xor_sync(0xffffffffu, sc, o);
        sc *= SCALE;

        float mn   = fmaxf(m, sc);
        float corr = __expf(m - mn);
        float p    = __expf(sc - mn);
        l = l * corr + p;
        acc.x = acc.x * corr + p * v4.x;
        acc.y = acc.y * corr + p * v4.y;
        acc.z = acc.z * corr + p * v4.z;
        acc.w = acc.w * corr + p * v4.w;
        m = mn;
    }

    const int pidx = ((b * H_ + h) * SPLITS + split) * 4 + warp;
    if (lane == 0) { g_pm[pidx] = m; g_pl[pidx] = l; }
    *(float4*)(g_pctx + (size_t)pidx * D_ + lane * 4) = acc;
}

// ---------------------------------------------------------------------------
// Combine NPART partials per (b,h) into normalized context.
// ---------------------------------------------------------------------------
__global__ void combine_kernel(float* __restrict__ ctx) {
    const int bh = blockIdx.x;   // b*H + h
    const int d  = threadIdx.x;  // 0..127

    float M = -INFINITY;
#pragma unroll
    for (int p = 0; p < NPART; p++) M = fmaxf(M, g_pm[bh * NPART + p]);

    float L = 0.f, c = 0.f;
#pragma unroll
    for (int p = 0; p < NPART; p++) {
        float w = __expf(g_pm[bh * NPART + p] - M);
        L += w * g_pl[bh * NPART + p];
        c += w * g_pctx[(size_t)(bh * NPART + p) * D_ + d];
    }
    ctx[(size_t)bh * D_ + d] = c / L;   // ctx[b*E + h*128 + d] since E = H*D
}

// ---------------------------------------------------------------------------
extern "C" void kernel_launch(void* const* d_in, const int* in_sizes, int n_in,
                              void* d_out, int out_size) {
    const float* x  = (const float*)d_in[0];
    const float* kc = (const float*)d_in[1];
    const float* vc = (const float*)d_in[2];
    const float* Wq = (const float*)d_in[3];
    const float* bq = (const float*)d_in[4];
    // Wk/bk/Wv/bv (d_in[5..8]) are dead in the reference — never used.
    const float* Wo = (const float*)d_in[9];
    const float* bo = (const float*)d_in[10];

    float* out = (float*)d_out;
    const size_t cache_elems = (size_t)B_ * S_ * H_ * D_;

    float* outk = nullptr;
    float* outv = nullptr;
    if ((size_t)out_size >= (size_t)B_ * E_ + 2 * cache_elems) {
        outk = out + B_ * E_;
        outv = outk + cache_elems;
    }

    // 1) Q projection
    proj_kernel<<<E_ / 8, 256>>>(x, Wq, bq, g_q);

    // 2) Fused attention + cache copy-out
    dim3 ag(SPLITS, H_, B_);
    attn_kernel<<<ag, 128>>>(g_q, kc, vc, outk, outv);

    // 3) Combine split partials
    combine_kernel<<<B_ * H_, D_>>>(g_ctx);

    // 4) Output projection
    proj_kernel<<<E_ / 8, 256>>>(g_ctx, Wo, bo, out);
}

// round 13
// speedup vs baseline: 1.3139x; 1.1721x over previous
#include <cuda_runtime.h>
#include <math.h>

#define B_  16
#define S_  4096
#define E_  2048
#define H_  16
#define D_  128
#define SPLITS 8
#define NPART (SPLITS * 4)        // 4 warps per block each emit a partial
#define SCALE 0.08838834764831845f // 1/sqrt(128)

// ---- scratch (no allocation allowed) ----
__device__ float g_q[B_ * E_];
__device__ float g_ctx[B_ * E_];
__device__ float g_pm[B_ * H_ * NPART];
__device__ float g_pl[B_ * H_ * NPART];
__device__ float g_pctx[B_ * H_ * NPART * D_];

// ---------------------------------------------------------------------------
// Projection: out[b,e] = sum_i x[b,i] * W[e,i] + bias[e]
// One warp per output column e. float4 loads + full unroll of the 16 chunks
// so ptxas front-batches the W loads (high MLP). W uses default caching so it
// stays L2-resident across graph replays now that the attention stream is
// marked evict-first.
// ---------------------------------------------------------------------------
__global__ void __launch_bounds__(256) proj_kernel(
        const float* __restrict__ x,
        const float* __restrict__ W,
        const float* __restrict__ bias,
        float* __restrict__ out) {
    const int e    = blockIdx.x * 8 + (threadIdx.x >> 5);
    const int lane = threadIdx.x & 31;

    const float4* __restrict__ w4 = (const float4*)(W + (size_t)e * E_);
    const float4* __restrict__ x4 = (const float4*)x;

    float acc[B_];
#pragma unroll
    for (int b = 0; b < B_; b++) acc[b] = 0.f;

#pragma unroll
    for (int c = 0; c < E_ / 128; c++) {           // 16 chunks, fully unrolled
        const int idx = c * 32 + lane;
        float4 w = w4[idx];
#pragma unroll
        for (int b = 0; b < B_; b++) {
            float4 xv = x4[b * (E_ / 4) + idx];
            acc[b] += w.x * xv.x + w.y * xv.y + w.z * xv.z + w.w * xv.w;
        }
    }

    const float bv = bias[e];
#pragma unroll
    for (int b = 0; b < B_; b++) {
        float v = acc[b];
#pragma unroll
        for (int off = 16; off > 0; off >>= 1) v += __shfl_xor_sync(0xffffffffu, v, off);
        if (lane == 0) out[b * E_ + e] = v + bv;
    }
}

// ---------------------------------------------------------------------------
// Fused flash-decode split-S attention. Each warp handles 128 rows of its
// (b,h,split) chunk with an online softmax; k/v float4s are simultaneously
// streamed to the d_out cache regions (each element touched exactly once).
// All streaming traffic is evict-first (__ldcs/__stcs): it is touched exactly
// once, so allocating it in L2 only evicts the projection weights and burns
// LTS slots.
// ---------------------------------------------------------------------------
__global__ void attn_kernel(const float* __restrict__ q,
                            const float* __restrict__ kc,
                            const float* __restrict__ vc,
                            float* __restrict__ outk,
                            float* __restrict__ outv) {
    const int split = blockIdx.x;
    const int h     = blockIdx.y;
    const int b     = blockIdx.z;
    const int warp  = threadIdx.x >> 5;
    const int lane  = threadIdx.x & 31;

    const size_t base = (size_t)b * S_ * H_ * D_ + (size_t)h * D_ + (size_t)lane * 4;

    float4 q4 = *(const float4*)(q + (size_t)b * E_ + h * D_ + lane * 4);

    float  m = -INFINITY, l = 0.f;
    float4 acc = make_float4(0.f, 0.f, 0.f, 0.f);

    const int s0 = split * (S_ / SPLITS) + warp;
    const bool wr = (outk != nullptr);

#pragma unroll 4
    for (int i = 0; i < (S_ / SPLITS) / 4; i++) {
        const int s = s0 + 4 * i;
        const size_t off = base + (size_t)s * (H_ * D_);
        float4 k4 = __ldcs((const float4*)(kc + off));
        float4 v4 = __ldcs((const float4*)(vc + off));
        if (wr) {
            __stcs((float4*)(outk + off), k4);
            __stcs((float4*)(outv + off), v4);
        }
        float sc = q4.x * k4.x + q4.y * k4.y + q4.z * k4.z + q4.w * k4.w;
#pragma unroll
        for (int o = 16; o > 0; o >>= 1) sc += __shfl_xor_sync(0xffffffffu, sc, o);
        sc *= SCALE;

        float mn   = fmaxf(m, sc);
        float corr = __expf(m - mn);
        float p    = __expf(sc - mn);
        l = l * corr + p;
        acc.x = acc.x * corr + p * v4.x;
        acc.y = acc.y * corr + p * v4.y;
        acc.z = acc.z * corr + p * v4.z;
        acc.w = acc.w * corr + p * v4.w;
        m = mn;
    }

    const int pidx = ((b * H_ + h) * SPLITS + split) * 4 + warp;
    if (lane == 0) { g_pm[pidx] = m; g_pl[pidx] = l; }
    *(float4*)(g_pctx + (size_t)pidx * D_ + lane * 4) = acc;
}

// ---------------------------------------------------------------------------
// Combine NPART partials per (b,h) into normalized context.
// ---------------------------------------------------------------------------
__global__ void combine_kernel(float* __restrict__ ctx) {
    const int bh = blockIdx.x;   // b*H + h
    const int d  = threadIdx.x;  // 0..127

    float M = -INFINITY;
#pragma unroll
    for (int p = 0; p < NPART; p++) M = fmaxf(M, g_pm[bh * NPART + p]);

    float L = 0.f, c = 0.f;
#pragma unroll
    for (int p = 0; p < NPART; p++) {
        float w = __expf(g_pm[bh * NPART + p] - M);
        L += w * g_pl[bh * NPART + p];
        c += w * g_pctx[(size_t)(bh * NPART + p) * D_ + d];
    }
    ctx[(size_t)bh * D_ + d] = c / L;   // ctx[b*E + h*128 + d] since E = H*D
}

// ---------------------------------------------------------------------------
extern "C" void kernel_launch(void* const* d_in, const int* in_sizes, int n_in,
                              void* d_out, int out_size) {
    const float* x  = (const float*)d_in[0];
    const float* kc = (const float*)d_in[1];
    const float* vc = (const float*)d_in[2];
    const float* Wq = (const float*)d_in[3];
    const float* bq = (const float*)d_in[4];
    // Wk/bk/Wv/bv (d_in[5..8]) are dead in the reference — never used.
    const float* Wo = (const float*)d_in[9];
    const float* bo = (const float*)d_in[10];

    float* out = (float*)d_out;
    const size_t cache_elems = (size_t)B_ * S_ * H_ * D_;

    float* outk = nullptr;
    float* outv = nullptr;
    if ((size_t)out_size >= (size_t)B_ * E_ + 2 * cache_elems) {
        outk = out + B_ * E_;
        outv = outk + cache_elems;
    }

    // 1) Q projection
    proj_kernel<<<E_ / 8, 256>>>(x, Wq, bq, g_q);

    // 2) Fused attention + cache copy-out
    dim3 ag(SPLITS, H_, B_);
    attn_kernel<<<ag, 128>>>(g_q, kc, vc, outk, outv);

    // 3) Combine split partials
    combine_kernel<<<B_ * H_, D_>>>(g_ctx);

    // 4) Output projection
    proj_kernel<<<E_ / 8, 256>>>(g_ctx, Wo, bo, out);
}